// round 2
// baseline (speedup 1.0000x reference)
#include <cuda_runtime.h>
#include <math.h>

#define NB 2048

// ---------------- static device scratch (no allocations allowed) ----------------
__device__ float  g_bufA[7356416];   // ping buffer (max: block1 out 2048*8*449)
__device__ float  g_bufB[3407872];   // pong buffer (max: block4 out 2048*64*26)
__device__ float  g_bw1[128];
__device__ float  g_bw2[1152];
__device__ float  g_bw3[3456];
__device__ float  g_bw4[14336];
__device__ float  g_bw5[20480];
__device__ float  g_bw6[12288];
__device__ float  g_bw7[13824];
__device__ float  g_bwfc[1080];
__device__ double g_ps1[32768];      // per-CTA stat partials (max 8*3592)
__device__ double g_ps2[32768];
__device__ float  g_bna[80];         // BN scale  a = gamma/sqrt(v+eps)
__device__ float  g_bnc[80];         // BN offset c = beta - m*a

// ---------------- weight binarization: bw = mean|w| * sign(w), per out-channel ----------------
__global__ void binw_kernel(const float* __restrict__ w, float* __restrict__ bw, int IK)
{
    const int o = blockIdx.x;
    __shared__ double sd[256];
    double acc = 0.0;
    for (int i = threadIdx.x; i < IK; i += 256) acc += (double)fabsf(w[o * IK + i]);
    sd[threadIdx.x] = acc;
    __syncthreads();
    for (int s = 128; s > 0; s >>= 1) {
        if (threadIdx.x < s) sd[threadIdx.x] += sd[threadIdx.x + s];
        __syncthreads();
    }
    __shared__ float ssc;
    if (threadIdx.x == 0) ssc = (float)(sd[0] / (double)IK);
    __syncthreads();
    const float sc = ssc;
    for (int i = threadIdx.x; i < IK; i += 256) {
        float v = w[o * IK + i];
        bw[o * IK + i] = (v > 0.f) ? sc : ((v < 0.f) ? -sc : 0.f);
    }
}

// ---------------- fused conv1d + maxpool + per-CTA BN-stat partials ----------------
// Thread: one (n, lp) position, CO_T output channels. Input window lives in registers.
template <int CIN, int COUT, int CO_T, int K, int STR, int PAD, int PK, int PS, int LIN, int LP>
__global__ void __launch_bounds__(256) conv_pool_kernel(
    const float* __restrict__ in, float* __restrict__ out,
    const float* __restrict__ w,
    double* __restrict__ ps1, double* __restrict__ ps2)
{
    constexpr int WL = (PK - 1) * PS * STR + (K > PS * STR ? K : PS * STR);
    constexpr int G  = (NB / 256) * LP;              // CTAs along x (exact)

    __shared__ float sw[CO_T * CIN * K];
    const int cob = blockIdx.y * CO_T;
    for (int i = threadIdx.x; i < CO_T * CIN * K; i += 256)
        sw[i] = w[cob * CIN * K + i];
    __syncthreads();

    const int idx = blockIdx.x * 256 + threadIdx.x;  // < NB*LP always (exact grid)
    const int n   = idx / LP;
    const int lp  = idx - n * LP;
    const float* __restrict__ inb = in + (long long)n * CIN * LIN;
    const int base0 = lp * PS * STR - PAD;

    float acc[CO_T][PK];
#pragma unroll
    for (int c = 0; c < CO_T; c++)
#pragma unroll
        for (int j = 0; j < PK; j++) acc[c][j] = 0.f;

#pragma unroll 1
    for (int ci = 0; ci < CIN; ++ci) {
        constexpr int WREAL = (PK - 1) * STR + K;    // actual span needed
        float win[WREAL];
        const float* __restrict__ ip = inb + ci * LIN;
#pragma unroll
        for (int t = 0; t < WREAL; t++) {
            int p = base0 + t;
            win[t] = (p >= 0 && p < LIN) ? ip[p] : 0.f;
        }
#pragma unroll
        for (int c = 0; c < CO_T; c++) {
#pragma unroll
            for (int k = 0; k < K; k++) {
                float wv = sw[(c * CIN + ci) * K + k];
#pragma unroll
                for (int j = 0; j < PK; j++)
                    acc[c][j] = fmaf(win[j * STR + k], wv, acc[c][j]);
            }
        }
    }
    (void)sizeof(char[WL >= 0 ? 1 : 1]);

    __shared__ double sh1[8], sh2[8];
    const int lane = threadIdx.x & 31;
    const int wid  = threadIdx.x >> 5;

#pragma unroll
    for (int c = 0; c < CO_T; c++) {
        float m = acc[c][0];
#pragma unroll
        for (int j = 1; j < PK; j++) m = fmaxf(m, acc[c][j]);
        out[((long long)n * COUT + cob + c) * LP + lp] = m;

        // deterministic stat partials: warp shuffle tree -> fixed serial combine
        double v1 = (double)m;
        double v2 = v1 * v1;
#pragma unroll
        for (int off = 16; off > 0; off >>= 1) {
            v1 += __shfl_down_sync(0xFFFFFFFFu, v1, off);
            v2 += __shfl_down_sync(0xFFFFFFFFu, v2, off);
        }
        if (lane == 0) { sh1[wid] = v1; sh2[wid] = v2; }
        __syncthreads();
        if (threadIdx.x == 0) {
            double t1 = 0.0, t2 = 0.0;
#pragma unroll
            for (int q = 0; q < 8; q++) { t1 += sh1[q]; t2 += sh2[q]; }
            ps1[(cob + c) * G + blockIdx.x] = t1;
            ps2[(cob + c) * G + blockIdx.x] = t2;
        }
        __syncthreads();
    }
}

// ---------------- BN stat finalize: per channel, deterministic ----------------
__global__ void stats_fin_kernel(
    const double* __restrict__ ps1, const double* __restrict__ ps2,
    const float* __restrict__ gamma, const float* __restrict__ beta,
    float* __restrict__ bna, float* __restrict__ bnc, int G, double invcnt)
{
    const int ch = blockIdx.x;
    __shared__ double s1[256], s2[256];
    double a1 = 0.0, a2 = 0.0;
    for (int i = threadIdx.x; i < G; i += 256) {
        a1 += ps1[ch * G + i];
        a2 += ps2[ch * G + i];
    }
    s1[threadIdx.x] = a1; s2[threadIdx.x] = a2;
    __syncthreads();
    for (int s = 128; s > 0; s >>= 1) {
        if (threadIdx.x < s) { s1[threadIdx.x] += s1[threadIdx.x + s]; s2[threadIdx.x] += s2[threadIdx.x + s]; }
        __syncthreads();
    }
    if (threadIdx.x == 0) {
        double m = s1[0] * invcnt;
        double v = s2[0] * invcnt - m * m;
        if (v < 0.0) v = 0.0;
        double inv = 1.0 / sqrt(v + 1e-5);
        double a = (double)gamma[ch] * inv;
        bna[ch] = (float)a;
        bnc[ch] = (float)((double)beta[ch] - m * a);
    }
}

// ---------------- BN apply + sign (in place) ----------------
template <int C, int LP>
__global__ void bn_sign_kernel(float* __restrict__ x,
                               const float* __restrict__ a, const float* __restrict__ c)
{
    const int idx = blockIdx.x * 256 + threadIdx.x;  // exact grid
    const int ch  = (idx / LP) % C;
    float v = fmaf(a[ch], x[idx], c[ch]);
    x[idx] = (v > 0.f) ? 1.f : ((v < 0.f) ? -1.f : 0.f);
}

// ---------------- FC: out[n][j] = sum_f act[n][f] * bwfc[j][f] ----------------
__global__ void fc_kernel(const float* __restrict__ act, const float* __restrict__ bw,
                          float* __restrict__ out)
{
    const int idx = blockIdx.x * 256 + threadIdx.x;
    if (idx >= NB * 5) return;
    const int n = idx / 5, j = idx - n * 5;
    const float* __restrict__ a  = act + n * 216;
    const float* __restrict__ wv = bw + j * 216;
    float s = 0.f;
#pragma unroll 8
    for (int f = 0; f < 216; ++f) s = fmaf(a[f], wv[f], s);
    out[idx] = s;
}

// ---------------- launch ----------------
extern "C" void kernel_launch(void* const* d_in, const int* in_sizes, int n_in,
                              void* d_out, int out_size)
{
    const float* x  = (const float*)d_in[0];
    const float* w[7]; const float* g[7]; const float* b[7];

    // Input order follows setup_inputs() dict: x, (w1,g1,b1), (w2,g2,b2), ..., wfc
    // Defensive: detect grouped order (x, w1..w7, g1..g7, b1..b7, wfc) via in_sizes[2]:
    // interleaved => g1 (8 elems); grouped => w3 (3456 elems).
    const bool interleaved = (in_sizes[2] == 8);
    for (int i = 0; i < 7; i++) {
        if (interleaved) {
            w[i] = (const float*)d_in[1 + 3 * i];
            g[i] = (const float*)d_in[2 + 3 * i];
            b[i] = (const float*)d_in[3 + 3 * i];
        } else {
            w[i] = (const float*)d_in[1 + i];
            g[i] = (const float*)d_in[8 + i];
            b[i] = (const float*)d_in[15 + i];
        }
    }
    const float* wfc = (const float*)d_in[22];
    float* out = (float*)d_out;

    float *bufA, *bufB, *bw1, *bw2, *bw3, *bw4, *bw5, *bw6, *bw7, *bwfc, *bna, *bnc;
    double *ps1, *ps2;
    cudaGetSymbolAddress((void**)&bufA, g_bufA);
    cudaGetSymbolAddress((void**)&bufB, g_bufB);
    cudaGetSymbolAddress((void**)&bw1, g_bw1);
    cudaGetSymbolAddress((void**)&bw2, g_bw2);
    cudaGetSymbolAddress((void**)&bw3, g_bw3);
    cudaGetSymbolAddress((void**)&bw4, g_bw4);
    cudaGetSymbolAddress((void**)&bw5, g_bw5);
    cudaGetSymbolAddress((void**)&bw6, g_bw6);
    cudaGetSymbolAddress((void**)&bw7, g_bw7);
    cudaGetSymbolAddress((void**)&bwfc, g_bwfc);
    cudaGetSymbolAddress((void**)&ps1, g_ps1);
    cudaGetSymbolAddress((void**)&ps2, g_ps2);
    cudaGetSymbolAddress((void**)&bna, g_bna);
    cudaGetSymbolAddress((void**)&bnc, g_bnc);

    // binarize weights
    binw_kernel<<<8,  256>>>(w[0], bw1, 1 * 16);
    binw_kernel<<<12, 256>>>(w[1], bw2, 8 * 12);
    binw_kernel<<<32, 256>>>(w[2], bw3, 12 * 9);
    binw_kernel<<<64, 256>>>(w[3], bw4, 32 * 7);
    binw_kernel<<<64, 256>>>(w[4], bw5, 64 * 5);
    binw_kernel<<<64, 256>>>(w[5], bw6, 64 * 3);
    binw_kernel<<<72, 256>>>(w[6], bw7, 64 * 3);
    binw_kernel<<<5,  256>>>(wfc,  bwfc, 216);

    // ---- block 1: C 1->8, k16 s2 p7, pool 8/4. 3600 -> 1800 -> 449
    conv_pool_kernel<1, 8, 4, 16, 2, 7, 8, 4, 3600, 449>
        <<<dim3(8 * 449, 2), 256>>>(x, bufA, bw1, ps1, ps2);
    stats_fin_kernel<<<8, 256>>>(ps1, ps2, g[0], b[0], bna, bnc, 8 * 449, 1.0 / (2048.0 * 449.0));
    bn_sign_kernel<8, 449><<<8 * 8 * 449, 256>>>(bufA, bna, bnc);

    // ---- block 2: 8->12, k12 s2 p5, pool 4/2. 449 -> 224 -> 111
    conv_pool_kernel<8, 12, 4, 12, 2, 5, 4, 2, 449, 111>
        <<<dim3(8 * 111, 3), 256>>>(bufA, bufB, bw2, ps1, ps2);
    stats_fin_kernel<<<12, 256>>>(ps1, ps2, g[1], b[1], bna, bnc, 8 * 111, 1.0 / (2048.0 * 111.0));
    bn_sign_kernel<12, 111><<<8 * 12 * 111, 256>>>(bufB, bna, bnc);

    // ---- block 3: 12->32, k9 s1 p4, pool 5/2. 111 -> 111 -> 54
    conv_pool_kernel<12, 32, 4, 9, 1, 4, 5, 2, 111, 54>
        <<<dim3(8 * 54, 8), 256>>>(bufB, bufA, bw3, ps1, ps2);
    stats_fin_kernel<<<32, 256>>>(ps1, ps2, g[2], b[2], bna, bnc, 8 * 54, 1.0 / (2048.0 * 54.0));
    bn_sign_kernel<32, 54><<<8 * 32 * 54, 256>>>(bufA, bna, bnc);

    // ---- block 4: 32->64, k7 s1 p3, pool 4/2. 54 -> 54 -> 26
    conv_pool_kernel<32, 64, 8, 7, 1, 3, 4, 2, 54, 26>
        <<<dim3(8 * 26, 8), 256>>>(bufA, bufB, bw4, ps1, ps2);
    stats_fin_kernel<<<64, 256>>>(ps1, ps2, g[3], b[3], bna, bnc, 8 * 26, 1.0 / (2048.0 * 26.0));
    bn_sign_kernel<64, 26><<<8 * 64 * 26, 256>>>(bufB, bna, bnc);

    // ---- block 5: 64->64, k5 s1 p2, pool 2/2. 26 -> 26 -> 13
    conv_pool_kernel<64, 64, 8, 5, 1, 2, 2, 2, 26, 13>
        <<<dim3(8 * 13, 8), 256>>>(bufB, bufA, bw5, ps1, ps2);
    stats_fin_kernel<<<64, 256>>>(ps1, ps2, g[4], b[4], bna, bnc, 8 * 13, 1.0 / (2048.0 * 13.0));
    bn_sign_kernel<64, 13><<<8 * 64 * 13, 256>>>(bufA, bna, bnc);

    // ---- block 6: 64->64, k3 s1 p1, pool 2/2. 13 -> 13 -> 6
    conv_pool_kernel<64, 64, 8, 3, 1, 1, 2, 2, 13, 6>
        <<<dim3(8 * 6, 8), 256>>>(bufA, bufB, bw6, ps1, ps2);
    stats_fin_kernel<<<64, 256>>>(ps1, ps2, g[5], b[5], bna, bnc, 8 * 6, 1.0 / (2048.0 * 6.0));
    bn_sign_kernel<64, 6><<<8 * 64 * 6, 256>>>(bufB, bna, bnc);

    // ---- block 7: 64->72, k3 s1 p1, pool 2/2. 6 -> 6 -> 3
    conv_pool_kernel<64, 72, 8, 3, 1, 1, 2, 2, 6, 3>
        <<<dim3(8 * 3, 9), 256>>>(bufB, bufA, bw7, ps1, ps2);
    stats_fin_kernel<<<72, 256>>>(ps1, ps2, g[6], b[6], bna, bnc, 8 * 3, 1.0 / (2048.0 * 3.0));
    bn_sign_kernel<72, 3><<<8 * 72 * 3, 256>>>(bufA, bna, bnc);

    // ---- FC: [2048,216] @ [5,216]^T
    fc_kernel<<<(NB * 5 + 255) / 256, 256>>>(bufA, bwfc, out);
}

// round 3
// speedup vs baseline: 3.8370x; 3.8370x over previous
#include <cuda_runtime.h>
#include <math.h>

#define NB 2048

typedef unsigned int       u32;
typedef unsigned long long u64;

// ---------------- static device scratch ----------------
__device__ float g_bufM[7356416];      // float conv/pool outputs (max 2048*8*449)
__device__ u64   g_bufP[919552];       // packed activations (max 2048*449 words)
__device__ float g_bw1[128];           // block1 binarized weights (8*16)
__device__ float g_bwfc[1080];         // FC binarized weights (5*216)
__device__ u32   g_wp2[144];           // 12*12
__device__ u32   g_wp3[288];           // 32*9
__device__ u32   g_wp4[448];           // 64*7
__device__ u64   g_wp5[320];           // 64*5
__device__ u64   g_wp6[192];           // 64*3
__device__ u64   g_wp7[216];           // 72*3
__device__ float g_scales[320];        // per-channel weight scales, layers 2-7
__device__ double g_psd1[28736];       // block1 stat partials (8*3592)
__device__ double g_psd2[28736];
__device__ long long g_psl1[16384];    // int stat partials (max 32*432=13824)
__device__ long long g_psl2[16384];
__device__ float g_bna[80];
__device__ float g_bnc[80];

__device__ __forceinline__ int popc_w(u32 x) { return __popc(x); }
__device__ __forceinline__ int popc_w(u64 x) { return __popcll(x); }

// ---------------- all weight binarization in ONE kernel ----------------
// block = one output channel of one layer. 321 blocks, 64 threads each.
__global__ void binw_all_kernel(
    const float* w1, const float* w2, const float* w3, const float* w4,
    const float* w5, const float* w6, const float* w7, const float* wfc,
    float* bw1, u32* wp2, u32* wp3, u32* wp4, u64* wp5, u64* wp6, u64* wp7,
    float* bwfc, float* scales)
{
    const int starts[9] = {0, 8, 20, 52, 116, 180, 244, 316, 321};
    const int CINs[8]   = {1, 8, 12, 32, 64, 64, 64, 216};
    const int Ks[8]     = {16, 12, 9, 7, 5, 3, 3, 1};
    const int soff[8]   = {0, 0, 12, 44, 108, 172, 236, 0};
    const float* ws[8]  = {w1, w2, w3, w4, w5, w6, w7, wfc};

    const int bx = blockIdx.x;
    int layer = 0;
    while (bx >= starts[layer + 1]) layer++;
    const int o   = bx - starts[layer];
    const int CIN = CINs[layer], K = Ks[layer], IK = CIN * K;
    const float* wrow = ws[layer] + o * IK;
    const int tid = threadIdx.x;

    __shared__ double sd[64];
    double acc = 0.0;
    for (int i = tid; i < IK; i += 64) acc += (double)fabsf(wrow[i]);
    sd[tid] = acc;
    __syncthreads();
    for (int s = 32; s > 0; s >>= 1) {
        if (tid < s) sd[tid] += sd[tid + s];
        __syncthreads();
    }
    const float scale = (float)(sd[0] / (double)IK);

    if (layer == 0) {
        for (int i = tid; i < IK; i += 64) {
            float v = wrow[i];
            bw1[o * IK + i] = (v > 0.f) ? scale : ((v < 0.f) ? -scale : 0.f);
        }
    } else if (layer == 7) {
        for (int i = tid; i < IK; i += 64) {
            float v = wrow[i];
            bwfc[o * IK + i] = (v > 0.f) ? scale : ((v < 0.f) ? -scale : 0.f);
        }
    } else {
        if (tid == 0) scales[soff[layer] + o] = scale;
        if (layer <= 3) {
            u32* wp = (layer == 1) ? wp2 : (layer == 2) ? wp3 : wp4;
            for (int k = tid; k < K; k += 64) {
                u32 word = 0;
                for (int ci = 0; ci < CIN; ci++)
                    if (wrow[ci * K + k] > 0.f) word |= (1u << ci);
                wp[o * K + k] = word;
            }
        } else {
            u64* wp = (layer == 4) ? wp5 : (layer == 5) ? wp6 : wp7;
            for (int k = tid; k < K; k += 64) {
                u64 word = 0;
                for (int ci = 0; ci < CIN; ci++)
                    if (wrow[ci * K + k] > 0.f) word |= (1ull << ci);
                wp[o * K + k] = word;
            }
        }
    }
}

// ---------------- block 1: fp32 conv + maxpool + stat partials ----------------
__global__ void __launch_bounds__(256) conv1_kernel(
    const float* __restrict__ x, float* __restrict__ out,
    const float* __restrict__ bw, double* __restrict__ ps1, double* __restrict__ ps2)
{
    constexpr int K = 16, STR = 2, PAD = 7, PK = 8, PS = 4, LIN = 3600, LP = 449, CO = 8;
    constexpr int WREAL = (PK - 1) * STR + K;   // 30
    __shared__ float sw[CO * K];
    for (int i = threadIdx.x; i < CO * K; i += 256) sw[i] = bw[i];
    __syncthreads();

    const int idx = blockIdx.x * 256 + threadIdx.x;   // exact grid
    const int n = idx / LP, lp = idx - n * LP;
    const int base0 = lp * PS * STR - PAD;
    const float* __restrict__ ip = x + (size_t)n * LIN;

    float win[WREAL];
#pragma unroll
    for (int t = 0; t < WREAL; t++) {
        int p = base0 + t;
        win[t] = (p >= 0 && p < LIN) ? ip[p] : 0.f;
    }
    float acc[CO][PK];
#pragma unroll
    for (int c = 0; c < CO; c++)
#pragma unroll
        for (int j = 0; j < PK; j++) acc[c][j] = 0.f;
#pragma unroll
    for (int c = 0; c < CO; c++)
#pragma unroll
        for (int k = 0; k < K; k++) {
            float wv = sw[c * K + k];
#pragma unroll
            for (int j = 0; j < PK; j++)
                acc[c][j] = fmaf(win[j * STR + k], wv, acc[c][j]);
        }

    __shared__ float sh1[8][CO], sh2[8][CO];
    const int lane = threadIdx.x & 31, wid = threadIdx.x >> 5;
#pragma unroll
    for (int c = 0; c < CO; c++) {
        float m = acc[c][0];
#pragma unroll
        for (int j = 1; j < PK; j++) m = fmaxf(m, acc[c][j]);
        out[((size_t)n * CO + c) * LP + lp] = m;
        float f1 = m, f2 = m * m;
#pragma unroll
        for (int off = 16; off > 0; off >>= 1) {
            f1 += __shfl_down_sync(0xFFFFFFFFu, f1, off);
            f2 += __shfl_down_sync(0xFFFFFFFFu, f2, off);
        }
        if (lane == 0) { sh1[wid][c] = f1; sh2[wid][c] = f2; }
    }
    __syncthreads();
    if (threadIdx.x < CO) {
        double t1 = 0.0, t2 = 0.0;
#pragma unroll
        for (int q = 0; q < 8; q++) { t1 += (double)sh1[q][threadIdx.x]; t2 += (double)sh2[q][threadIdx.x]; }
        ps1[threadIdx.x * gridDim.x + blockIdx.x] = t1;
        ps2[threadIdx.x * gridDim.x + blockIdx.x] = t2;
    }
}

// ---------------- XNOR-popcount conv + maxpool + exact int stat partials ----------------
template <typename WT, int CIN, int COUT, int CO_T, int K, int STR, int PAD, int PK, int PS, int LIN, int LP>
__global__ void __launch_bounds__(256) conv_popc_kernel(
    const WT* __restrict__ inP, float* __restrict__ out,
    const WT* __restrict__ wp, const float* __restrict__ scales,
    long long* __restrict__ ps1, long long* __restrict__ ps2)
{
    constexpr int WREAL = (PK - 1) * STR + K;
    constexpr WT  MCIN  = (CIN >= (int)(8 * sizeof(WT))) ? (WT)~(WT)0 : (WT)(((WT)1 << CIN) - 1);

    __shared__ WT sw[CO_T * K];
    __shared__ float ssc[CO_T];
    const int cob = blockIdx.y * CO_T;
    for (int i = threadIdx.x; i < CO_T * K; i += 256) sw[i] = wp[cob * K + i];
    if (threadIdx.x < CO_T) ssc[threadIdx.x] = scales[cob + threadIdx.x];
    __syncthreads();

    const int idx = blockIdx.x * 256 + threadIdx.x;   // exact grid
    const int n = idx / LP, lp = idx - n * LP;
    const int base0 = lp * PS * STR - PAD;
    const WT* __restrict__ ib = inP + (size_t)n * LIN;

    WT win[WREAL], msk[WREAL];
    int cnt[PK];
#pragma unroll
    for (int t = 0; t < WREAL; t++) {
        int p = base0 + t;
        bool v = (p >= 0 && p < LIN);
        win[t] = v ? ib[p] : (WT)0;
        msk[t] = v ? MCIN : (WT)0;
    }
#pragma unroll
    for (int j = 0; j < PK; j++) {
        int cc = 0;
#pragma unroll
        for (int k = 0; k < K; k++) cc += (msk[j * STR + k] != 0) ? CIN : 0;
        cnt[j] = cc;
    }

    int P[CO_T][PK];
#pragma unroll
    for (int c = 0; c < CO_T; c++)
#pragma unroll
        for (int j = 0; j < PK; j++) P[c][j] = 0;

#pragma unroll
    for (int k = 0; k < K; k++) {
#pragma unroll
        for (int c = 0; c < CO_T; c++) {
            WT wk = sw[c * K + k];
#pragma unroll
            for (int j = 0; j < PK; j++) {
                int t = j * STR + k;
                P[c][j] += popc_w((WT)(~(win[t] ^ wk) & msk[t]));
            }
        }
    }

    __shared__ int sh1[8][CO_T];
    __shared__ int sh2[8][CO_T];
    const int lane = threadIdx.x & 31, wid = threadIdx.x >> 5;
#pragma unroll
    for (int c = 0; c < CO_T; c++) {
        int mS = 2 * P[c][0] - cnt[0];
#pragma unroll
        for (int j = 1; j < PK; j++) {
            int s = 2 * P[c][j] - cnt[j];
            mS = (s > mS) ? s : mS;
        }
        out[((size_t)n * COUT + cob + c) * LP + lp] = ssc[c] * (float)mS;
        int v1 = mS, v2 = mS * mS;
#pragma unroll
        for (int off = 16; off > 0; off >>= 1) {
            v1 += __shfl_down_sync(0xFFFFFFFFu, v1, off);
            v2 += __shfl_down_sync(0xFFFFFFFFu, v2, off);
        }
        if (lane == 0) { sh1[wid][c] = v1; sh2[wid][c] = v2; }
    }
    __syncthreads();
    if (threadIdx.x < CO_T) {
        long long t1 = 0, t2 = 0;
#pragma unroll
        for (int q = 0; q < 8; q++) { t1 += sh1[q][threadIdx.x]; t2 += sh2[q][threadIdx.x]; }
        ps1[(size_t)(cob + threadIdx.x) * gridDim.x + blockIdx.x] = t1;
        ps2[(size_t)(cob + threadIdx.x) * gridDim.x + blockIdx.x] = t2;
    }
}

// ---------------- BN finalize (double partials, block 1) ----------------
__global__ void stats_fin_d(const double* __restrict__ ps1, const double* __restrict__ ps2,
                            const float* __restrict__ gamma, const float* __restrict__ beta,
                            float* __restrict__ bna, float* __restrict__ bnc, int G, double invcnt)
{
    const int ch = blockIdx.x;
    __shared__ double s1[256], s2[256];
    double a1 = 0.0, a2 = 0.0;
    for (int i = threadIdx.x; i < G; i += 256) { a1 += ps1[ch * G + i]; a2 += ps2[ch * G + i]; }
    s1[threadIdx.x] = a1; s2[threadIdx.x] = a2;
    __syncthreads();
    for (int s = 128; s > 0; s >>= 1) {
        if (threadIdx.x < s) { s1[threadIdx.x] += s1[threadIdx.x + s]; s2[threadIdx.x] += s2[threadIdx.x + s]; }
        __syncthreads();
    }
    if (threadIdx.x == 0) {
        double m = s1[0] * invcnt;
        double v = s2[0] * invcnt - m * m;
        if (v < 0.0) v = 0.0;
        double a = (double)gamma[ch] / sqrt(v + 1e-5);
        bna[ch] = (float)a;
        bnc[ch] = (float)((double)beta[ch] - m * a);
    }
}

// ---------------- BN finalize (exact int partials, blocks 2-7) ----------------
__global__ void stats_fin_i(const long long* __restrict__ ps1, const long long* __restrict__ ps2,
                            const float* __restrict__ gamma, const float* __restrict__ beta,
                            const float* __restrict__ scales,
                            float* __restrict__ bna, float* __restrict__ bnc, int G, double invcnt)
{
    const int ch = blockIdx.x;
    __shared__ long long s1[256], s2[256];
    long long a1 = 0, a2 = 0;
    for (int i = threadIdx.x; i < G; i += 256) { a1 += ps1[ch * G + i]; a2 += ps2[ch * G + i]; }
    s1[threadIdx.x] = a1; s2[threadIdx.x] = a2;
    __syncthreads();
    for (int s = 128; s > 0; s >>= 1) {
        if (threadIdx.x < s) { s1[threadIdx.x] += s1[threadIdx.x + s]; s2[threadIdx.x] += s2[threadIdx.x + s]; }
        __syncthreads();
    }
    if (threadIdx.x == 0) {
        double sc = (double)scales[ch];
        double m  = sc * (double)s1[0] * invcnt;
        double e2 = sc * sc * (double)s2[0] * invcnt;
        double v  = e2 - m * m;
        if (v < 0.0) v = 0.0;
        double a = (double)gamma[ch] / sqrt(v + 1e-5);
        bna[ch] = (float)a;
        bnc[ch] = (float)((double)beta[ch] - m * a);
    }
}

// ---------------- BN + sign + channel-pack ----------------
template <typename WT, int C, int LP>
__global__ void __launch_bounds__(256) pack_kernel(
    const float* __restrict__ m, const float* __restrict__ a, const float* __restrict__ c,
    WT* __restrict__ outP)
{
    __shared__ float sa[C], sc[C];
    if (threadIdx.x < C) { sa[threadIdx.x] = a[threadIdx.x]; sc[threadIdx.x] = c[threadIdx.x]; }
    __syncthreads();
    const int idx = blockIdx.x * 256 + threadIdx.x;   // exact grid
    const int n = idx / LP, lp = idx - n * LP;
    WT word = 0;
#pragma unroll
    for (int co = 0; co < C; co++) {
        float v = fmaf(sa[co], m[((size_t)n * C + co) * LP + lp], sc[co]);
        if (v > 0.f) word |= ((WT)1 << co);
    }
    outP[(size_t)n * LP + lp] = word;
}

// ---------------- FC with fused BN+sign of block 7 ----------------
__global__ void fc_bn_kernel(const float* __restrict__ m7, const float* __restrict__ bwfc,
                             const float* __restrict__ a, const float* __restrict__ c,
                             float* __restrict__ out)
{
    __shared__ float sa[72], sc[72];
    if (threadIdx.x < 72) { sa[threadIdx.x] = a[threadIdx.x]; sc[threadIdx.x] = c[threadIdx.x]; }
    __syncthreads();
    const int idx = blockIdx.x * 256 + threadIdx.x;
    if (idx >= NB * 5) return;
    const int n = idx / 5, j = idx - n * 5;
    const float* __restrict__ mb = m7 + (size_t)n * 216;
    const float* __restrict__ wb = bwfc + j * 216;
    float s = 0.f;
#pragma unroll 4
    for (int co = 0; co < 72; co++) {
        float av = sa[co], cv = sc[co];
#pragma unroll
        for (int l = 0; l < 3; l++) {
            float v = fmaf(av, mb[co * 3 + l], cv);
            float sg = (v > 0.f) ? 1.f : ((v < 0.f) ? -1.f : 0.f);
            s = fmaf(sg, wb[co * 3 + l], s);
        }
    }
    out[n * 5 + j] = s;
}

// ---------------- launch ----------------
extern "C" void kernel_launch(void* const* d_in, const int* in_sizes, int n_in,
                              void* d_out, int out_size)
{
    const float* x = (const float*)d_in[0];
    const float* w[7]; const float* g[7]; const float* b[7];
    const bool interleaved = (in_sizes[2] == 8);
    for (int i = 0; i < 7; i++) {
        if (interleaved) {
            w[i] = (const float*)d_in[1 + 3 * i];
            g[i] = (const float*)d_in[2 + 3 * i];
            b[i] = (const float*)d_in[3 + 3 * i];
        } else {
            w[i] = (const float*)d_in[1 + i];
            g[i] = (const float*)d_in[8 + i];
            b[i] = (const float*)d_in[15 + i];
        }
    }
    const float* wfc = (const float*)d_in[22];
    float* out = (float*)d_out;

    float *bufM, *bw1, *bwfc, *scales, *bna, *bnc;
    u64 *bufP, *wp5, *wp6, *wp7;
    u32 *wp2, *wp3, *wp4;
    double *psd1, *psd2;
    long long *psl1, *psl2;
    cudaGetSymbolAddress((void**)&bufM, g_bufM);
    cudaGetSymbolAddress((void**)&bufP, g_bufP);
    cudaGetSymbolAddress((void**)&bw1, g_bw1);
    cudaGetSymbolAddress((void**)&bwfc, g_bwfc);
    cudaGetSymbolAddress((void**)&wp2, g_wp2);
    cudaGetSymbolAddress((void**)&wp3, g_wp3);
    cudaGetSymbolAddress((void**)&wp4, g_wp4);
    cudaGetSymbolAddress((void**)&wp5, g_wp5);
    cudaGetSymbolAddress((void**)&wp6, g_wp6);
    cudaGetSymbolAddress((void**)&wp7, g_wp7);
    cudaGetSymbolAddress((void**)&scales, g_scales);
    cudaGetSymbolAddress((void**)&psd1, g_psd1);
    cudaGetSymbolAddress((void**)&psd2, g_psd2);
    cudaGetSymbolAddress((void**)&psl1, g_psl1);
    cudaGetSymbolAddress((void**)&psl2, g_psl2);
    cudaGetSymbolAddress((void**)&bna, g_bna);
    cudaGetSymbolAddress((void**)&bnc, g_bnc);

    u32* bufP32 = (u32*)bufP;

    binw_all_kernel<<<321, 64>>>(w[0], w[1], w[2], w[3], w[4], w[5], w[6], wfc,
                                 bw1, wp2, wp3, wp4, wp5, wp6, wp7, bwfc, scales);

    // block 1 (fp32): 1->8, k16 s2 p7, pool 8/4, 3600->449
    conv1_kernel<<<3592, 256>>>(x, bufM, bw1, psd1, psd2);
    stats_fin_d<<<8, 256>>>(psd1, psd2, g[0], b[0], bna, bnc, 3592, 1.0 / (2048.0 * 449.0));
    pack_kernel<u32, 8, 449><<<3592, 256>>>(bufM, bna, bnc, bufP32);

    // block 2: 8->12, k12 s2 p5, pool 4/2, 449->111
    conv_popc_kernel<u32, 8, 12, 12, 12, 2, 5, 4, 2, 449, 111>
        <<<dim3(888, 1), 256>>>(bufP32, bufM, wp2, scales + 0, psl1, psl2);
    stats_fin_i<<<12, 256>>>(psl1, psl2, g[1], b[1], scales + 0, bna, bnc, 888, 1.0 / (2048.0 * 111.0));
    pack_kernel<u32, 12, 111><<<888, 256>>>(bufM, bna, bnc, bufP32);

    // block 3: 12->32, k9 s1 p4, pool 5/2, 111->54
    conv_popc_kernel<u32, 12, 32, 16, 9, 1, 4, 5, 2, 111, 54>
        <<<dim3(432, 2), 256>>>(bufP32, bufM, wp3, scales + 12, psl1, psl2);
    stats_fin_i<<<32, 256>>>(psl1, psl2, g[2], b[2], scales + 12, bna, bnc, 432, 1.0 / (2048.0 * 54.0));
    pack_kernel<u32, 32, 54><<<432, 256>>>(bufM, bna, bnc, bufP32);

    // block 4: 32->64, k7 s1 p3, pool 4/2, 54->26
    conv_popc_kernel<u32, 32, 64, 16, 7, 1, 3, 4, 2, 54, 26>
        <<<dim3(208, 4), 256>>>(bufP32, bufM, wp4, scales + 44, psl1, psl2);
    stats_fin_i<<<64, 256>>>(psl1, psl2, g[3], b[3], scales + 44, bna, bnc, 208, 1.0 / (2048.0 * 26.0));
    pack_kernel<u64, 64, 26><<<208, 256>>>(bufM, bna, bnc, bufP);

    // block 5: 64->64, k5 s1 p2, pool 2/2, 26->13
    conv_popc_kernel<u64, 64, 64, 16, 5, 1, 2, 2, 2, 26, 13>
        <<<dim3(104, 4), 256>>>(bufP, bufM, wp5, scales + 108, psl1, psl2);
    stats_fin_i<<<64, 256>>>(psl1, psl2, g[4], b[4], scales + 108, bna, bnc, 104, 1.0 / (2048.0 * 13.0));
    pack_kernel<u64, 64, 13><<<104, 256>>>(bufM, bna, bnc, bufP);

    // block 6: 64->64, k3 s1 p1, pool 2/2, 13->6
    conv_popc_kernel<u64, 64, 64, 16, 3, 1, 1, 2, 2, 13, 6>
        <<<dim3(48, 4), 256>>>(bufP, bufM, wp6, scales + 172, psl1, psl2);
    stats_fin_i<<<64, 256>>>(psl1, psl2, g[5], b[5], scales + 172, bna, bnc, 48, 1.0 / (2048.0 * 6.0));
    pack_kernel<u64, 64, 6><<<48, 256>>>(bufM, bna, bnc, bufP);

    // block 7: 64->72, k3 s1 p1, pool 2/2, 6->3
    conv_popc_kernel<u64, 64, 72, 24, 3, 1, 1, 2, 2, 6, 3>
        <<<dim3(24, 3), 256>>>(bufP, bufM, wp7, scales + 236, psl1, psl2);
    stats_fin_i<<<72, 256>>>(psl1, psl2, g[6], b[6], scales + 236, bna, bnc, 24, 1.0 / (2048.0 * 3.0));

    // FC with fused BN+sign: [2048,216] @ [5,216]^T
    fc_bn_kernel<<<(NB * 5 + 255) / 256, 256>>>(bufM, bwfc, bna, bnc, out);
}